// round 4
// baseline (speedup 1.0000x reference)
#include <cuda_runtime.h>
#include <cuda_bf16.h>
#include <math.h>

// Problem constants (fixed by reference)
constexpr int NN  = 100000;
constexpr int EE  = 1600000;
constexpr int FIN = 512;
constexpr int HH  = 128;
constexpr int CC  = 64;

// Scratch (device globals: allocation-free rule)
__device__ float g_h[(size_t)NN * HH];
__device__ float g_acc[(size_t)NN * HH];
__device__ float g_y[(size_t)NN * HH];
__device__ float g_dinv[NN];
__device__ float g_norm[EE];

#define BM 128
#define BK2 8

// ---------------------------------------------------------------------------
// Tiled SGEMM, double-buffered, 128xBN_x8 tile, TM=8 x TN_ per thread.
// Optional fused A-transform: A_eff = relu(A + Ah * dinv[row]^2)  (GCN
// self-loop + relu folded into the consumer GEMM's A load).
// ---------------------------------------------------------------------------
template <int BN_, int TN_, bool FUSE>
__global__ __launch_bounds__(256) void sgemm_t(
    const float* __restrict__ A, const float* __restrict__ Ah,
    const float* __restrict__ dinv,
    const float* __restrict__ B, const float* __restrict__ bias,
    float* __restrict__ C, int M, int K, int Nout, int relu)
{
    __shared__ __align__(16) float As[2][BK2][BM + 4];
    __shared__ __align__(16) float Bs[2][BK2][BN_];

    const int tid  = threadIdx.x;
    const int tcol = tid & 15;
    const int trow = tid >> 4;
    const int blockRow = blockIdx.x * BM;
    const int blockCol = blockIdx.y * BN_;

    float acc[8][TN_];
#pragma unroll
    for (int i = 0; i < 8; i++)
#pragma unroll
        for (int j = 0; j < TN_; j++) acc[i][j] = 0.f;

    // A-load: 128 rows x 2 float4 = 256 float4; one per thread.
    const int a_row = tid & 127;
    const int a_kq  = tid >> 7;             // 0/1 -> k offset 0/4
    const int a_grow = blockRow + a_row;
    const bool a_ok = (a_grow < M);
    float selfw = 0.f;
    if (FUSE && a_ok) { float di = dinv[a_grow]; selfw = di * di; }

    // B-load: 8 rows x BN_/4 float4.
    int b_row, b_cq; bool b_ok;
    if (BN_ == 128) { b_row = tid >> 5; b_cq = tid & 31; b_ok = true; }
    else            { b_row = tid >> 4; b_cq = tid & 15; b_ok = (tid < 128); }

    auto loadA = [&](int k0) -> float4 {
        if (!a_ok) return make_float4(0.f, 0.f, 0.f, 0.f);
        size_t idx = (size_t)a_grow * K + k0 + a_kq * 4;
        float4 v = *(const float4*)(A + idx);
        if (FUSE) {
            float4 hh = *(const float4*)(Ah + idx);
            v.x = fmaxf(fmaf(hh.x, selfw, v.x), 0.f);
            v.y = fmaxf(fmaf(hh.y, selfw, v.y), 0.f);
            v.z = fmaxf(fmaf(hh.z, selfw, v.z), 0.f);
            v.w = fmaxf(fmaf(hh.w, selfw, v.w), 0.f);
        }
        return v;
    };
    auto loadB = [&](int k0) -> float4 {
        if (!b_ok) return make_float4(0.f, 0.f, 0.f, 0.f);
        return *(const float4*)(B + (size_t)(k0 + b_row) * Nout + blockCol + b_cq * 4);
    };
    auto stA = [&](int buf, float4 v) {
        As[buf][a_kq * 4 + 0][a_row] = v.x;
        As[buf][a_kq * 4 + 1][a_row] = v.y;
        As[buf][a_kq * 4 + 2][a_row] = v.z;
        As[buf][a_kq * 4 + 3][a_row] = v.w;
    };
    auto stB = [&](int buf, float4 v) {
        if (b_ok) *(float4*)&Bs[buf][b_row][b_cq * 4] = v;
    };

    // prologue
    stA(0, loadA(0));
    stB(0, loadB(0));
    __syncthreads();

    int buf = 0;
    for (int k0 = BK2; k0 < K; k0 += BK2) {
        float4 a_pf = loadA(k0);
        float4 b_pf = loadB(k0);

#pragma unroll
        for (int kk = 0; kk < BK2; kk++) {
            const float4* ap = (const float4*)&As[buf][kk][trow * 8];
            float4 a0 = ap[0], a1 = ap[1];
            float a[8] = {a0.x, a0.y, a0.z, a0.w, a1.x, a1.y, a1.z, a1.w};
            float b[TN_];
            const float4* bp = (const float4*)&Bs[buf][kk][tcol * TN_];
            float4 bb0 = bp[0];
            b[0] = bb0.x; b[1] = bb0.y; b[2] = bb0.z; b[3] = bb0.w;
            if (TN_ == 8) {
                float4 bb1 = bp[1];
                b[4] = bb1.x; b[5] = bb1.y; b[6] = bb1.z; b[7] = bb1.w;
            }
#pragma unroll
            for (int i = 0; i < 8; i++)
#pragma unroll
                for (int j = 0; j < TN_; j++)
                    acc[i][j] = fmaf(a[i], b[j], acc[i][j]);
        }

        stA(buf ^ 1, a_pf);
        stB(buf ^ 1, b_pf);
        __syncthreads();
        buf ^= 1;
    }

    // last tile
#pragma unroll
    for (int kk = 0; kk < BK2; kk++) {
        const float4* ap = (const float4*)&As[buf][kk][trow * 8];
        float4 a0 = ap[0], a1 = ap[1];
        float a[8] = {a0.x, a0.y, a0.z, a0.w, a1.x, a1.y, a1.z, a1.w};
        float b[TN_];
        const float4* bp = (const float4*)&Bs[buf][kk][tcol * TN_];
        float4 bb0 = bp[0];
        b[0] = bb0.x; b[1] = bb0.y; b[2] = bb0.z; b[3] = bb0.w;
        if (TN_ == 8) {
            float4 bb1 = bp[1];
            b[4] = bb1.x; b[5] = bb1.y; b[6] = bb1.z; b[7] = bb1.w;
        }
#pragma unroll
        for (int i = 0; i < 8; i++)
#pragma unroll
            for (int j = 0; j < TN_; j++)
                acc[i][j] = fmaf(a[i], b[j], acc[i][j]);
    }

    // epilogue
    float bv[TN_];
#pragma unroll
    for (int j = 0; j < TN_; j++) bv[j] = bias[blockCol + tcol * TN_ + j];
#pragma unroll
    for (int i = 0; i < 8; i++) {
        int grow = blockRow + trow * 8 + i;
        if (grow >= M) continue;
        float* cp = C + (size_t)grow * Nout + blockCol + tcol * TN_;
#pragma unroll
        for (int q = 0; q < TN_ / 4; q++) {
            float4 v;
            v.x = acc[i][q * 4 + 0] + bv[q * 4 + 0];
            v.y = acc[i][q * 4 + 1] + bv[q * 4 + 1];
            v.z = acc[i][q * 4 + 2] + bv[q * 4 + 2];
            v.w = acc[i][q * 4 + 3] + bv[q * 4 + 3];
            if (relu) {
                v.x = fmaxf(v.x, 0.f); v.y = fmaxf(v.y, 0.f);
                v.z = fmaxf(v.z, 0.f); v.w = fmaxf(v.w, 0.f);
            }
            *(float4*)(cp + q * 4) = v;
        }
    }
}

// ---------------------------------------------------------------------------
// Graph preprocessing
// ---------------------------------------------------------------------------
__global__ void count_deg(const int* __restrict__ dst, float* __restrict__ deg, int E)
{
    int e = blockIdx.x * blockDim.x + threadIdx.x;
    if (e < E) atomicAdd(&deg[dst[e]], 1.0f);
}

__global__ void fin_deg(float* __restrict__ dinv, int n)
{
    int i = blockIdx.x * blockDim.x + threadIdx.x;
    if (i < n) dinv[i] = rsqrtf(dinv[i] + 1.0f);  // +1 for self-loop
}

__global__ void comp_norm(const int* __restrict__ src, const int* __restrict__ dst,
                          const float* __restrict__ dinv, float* __restrict__ norm, int E)
{
    int e = blockIdx.x * blockDim.x + threadIdx.x;
    if (e < E) norm[e] = dinv[src[e]] * dinv[dst[e]];
}

// ---------------------------------------------------------------------------
// Edge scatter: acc[dst] += h[src] * norm; one red.global.add.v4.f32 per lane.
// ---------------------------------------------------------------------------
__global__ __launch_bounds__(256) void scatter_edges(
    const float* __restrict__ h, const int* __restrict__ src,
    const int* __restrict__ dst, const float* __restrict__ norm,
    float* __restrict__ acc, int E)
{
    int t = blockIdx.x * blockDim.x + threadIdx.x;
    int e = t >> 5;
    if (e >= E) return;
    int lane = t & 31;
    int s = __ldg(src + e);
    int d = __ldg(dst + e);
    float nrm = __ldg(norm + e);
    float4 v = *(const float4*)(h + (size_t)s * HH + lane * 4);
    float* o = acc + (size_t)d * HH + lane * 4;
    asm volatile("red.global.add.v4.f32 [%0], {%1, %2, %3, %4};"
                 :: "l"(o), "f"(v.x * nrm), "f"(v.y * nrm),
                    "f"(v.z * nrm), "f"(v.w * nrm)
                 : "memory");
}

// ---------------------------------------------------------------------------
// log_softmax over C=64 classes; 1 warp per row, 2 classes per lane.
// ---------------------------------------------------------------------------
__global__ void log_softmax_k(const float* __restrict__ logits, float* __restrict__ out, int N)
{
    int row = blockIdx.x * blockDim.y + threadIdx.y;
    if (row >= N) return;
    int lane = threadIdx.x;
    const float* lr = logits + (size_t)row * CC;
    float v0 = lr[lane], v1 = lr[lane + 32];
    float m = fmaxf(v0, v1);
#pragma unroll
    for (int o = 16; o; o >>= 1) m = fmaxf(m, __shfl_xor_sync(0xffffffffu, m, o));
    float s = expf(v0 - m) + expf(v1 - m);
#pragma unroll
    for (int o = 16; o; o >>= 1) s += __shfl_xor_sync(0xffffffffu, s, o);
    float ls = m + logf(s);
    float* orow = out + (size_t)row * CC;
    orow[lane] = v0 - ls;
    orow[lane + 32] = v1 - ls;
}

// ---------------------------------------------------------------------------
// Launch
// ---------------------------------------------------------------------------
extern "C" void kernel_launch(void* const* d_in, const int* in_sizes, int n_in,
                              void* d_out, int out_size)
{
    const float* x     = (const float*)d_in[0];
    const int*   ei    = (const int*)d_in[1];
    const float* W0    = (const float*)d_in[2];
    const float* b0    = (const float*)d_in[3];
    const float* W1    = (const float*)d_in[4];
    const float* b1    = (const float*)d_in[5];
    const float* W2    = (const float*)d_in[6];
    const float* b2    = (const float*)d_in[7];
    const float* fc1_w = (const float*)d_in[8];
    const float* fc1_b = (const float*)d_in[9];
    const float* fc2_w = (const float*)d_in[10];
    const float* fc2_b = (const float*)d_in[11];
    const float* fc3_w = (const float*)d_in[12];
    const float* fc3_b = (const float*)d_in[13];

    const int N = in_sizes[0] / FIN;   // 100000
    const int E = in_sizes[1] / 2;     // 1600000
    const int* src = ei;
    const int* dst = ei + E;

    float *h_, *acc_, *y_, *dinv_, *norm_;
    cudaGetSymbolAddress((void**)&h_,    g_h);
    cudaGetSymbolAddress((void**)&acc_,  g_acc);
    cudaGetSymbolAddress((void**)&y_,    g_y);
    cudaGetSymbolAddress((void**)&dinv_, g_dinv);
    cudaGetSymbolAddress((void**)&norm_, g_norm);

    const int T = 256;
    dim3 grid_h((N + BM - 1) / BM, 1);      // BN=128 covers H
    dim3 grid_c((N + BM - 1) / BM, 1);      // BN=64 covers C

    // ---- graph normalization ----
    cudaMemsetAsync(dinv_, 0, (size_t)N * sizeof(float));
    count_deg<<<(E + T - 1) / T, T>>>(dst, dinv_, E);
    fin_deg<<<(N + T - 1) / T, T>>>(dinv_, N);
    comp_norm<<<(E + T - 1) / T, T>>>(src, dst, dinv_, norm_, E);

    const int scatter_blocks = (int)(((size_t)E * 32 + T - 1) / T);
    const size_t nh_bytes = (size_t)N * HH * sizeof(float);

    // ---- conv0: h_ = x @ W0 + b0 ; scatter h_ -> acc_ ----
    sgemm_t<128, 8, false><<<grid_h, T>>>(x, nullptr, nullptr, W0, b0, h_, N, FIN, HH, 0);
    cudaMemsetAsync(acc_, 0, nh_bytes);
    scatter_edges<<<scatter_blocks, T>>>(h_, src, dst, norm_, acc_, E);

    // ---- conv1: y_ = relu(acc_ + h_*w) @ W1 + b1 ; scatter y_ -> acc_ ----
    sgemm_t<128, 8, true><<<grid_h, T>>>(acc_, h_, dinv_, W1, b1, y_, N, HH, HH, 0);
    cudaMemsetAsync(acc_, 0, nh_bytes);
    scatter_edges<<<scatter_blocks, T>>>(y_, src, dst, norm_, acc_, E);

    // ---- conv2: h_ = relu(acc_ + y_*w) @ W2 + b2 ; scatter h_ -> acc_ ----
    sgemm_t<128, 8, true><<<grid_h, T>>>(acc_, y_, dinv_, W2, b2, h_, N, HH, HH, 0);
    cudaMemsetAsync(acc_, 0, nh_bytes);
    scatter_edges<<<scatter_blocks, T>>>(h_, src, dst, norm_, acc_, E);

    // ---- MLP: fc1 fused with conv2 finalize; fc2; fc3 ----
    sgemm_t<128, 8, true><<<grid_h, T>>>(acc_, h_, dinv_, fc1_w, fc1_b, y_, N, HH, HH, 1);
    sgemm_t<128, 8, false><<<grid_h, T>>>(y_, nullptr, nullptr, fc2_w, fc2_b, h_, N, HH, HH, 1);
    sgemm_t<64, 4, false><<<grid_c, T>>>(h_, nullptr, nullptr, fc3_w, fc3_b, y_, N, HH, CC, 0);

    // ---- log_softmax ----
    dim3 ls_block(32, 8);
    log_softmax_k<<<(N + 7) / 8, ls_block>>>(y_, (float*)d_out, N);
}

// round 7
// speedup vs baseline: 1.5491x; 1.5491x over previous
#include <cuda_runtime.h>
#include <cuda_bf16.h>
#include <math.h>
#include <stdint.h>

// Problem constants (fixed by reference)
constexpr int NN  = 100000;
constexpr int EE  = 1600000;
constexpr int FIN = 512;
constexpr int HH  = 128;
constexpr int CC  = 64;

// Scratch (device globals: allocation-free rule)
__device__ float g_h[(size_t)NN * HH];
__device__ float g_y[(size_t)NN * HH];
__device__ float g_dinv[NN];
__device__ int   g_rowptr[NN + 1];
__device__ int   g_cursor[NN];
__device__ int   g_csr_src[EE];
__device__ float g_csr_norm[EE];
__device__ int   g_bsum[256];

// ---------------------------------------------------------------------------
// Tiled SGEMM, double-buffered (R2-proven): C = A[MxK] @ B[KxNout] + bias.
// BM=128, BN=64, BK=16, TM=8, TN=4, 256 threads.
// ---------------------------------------------------------------------------
#define BM 128
#define BN 64
#define BK 16
#define TM 8
#define TN 4

__global__ __launch_bounds__(256) void sgemm_bias(
    const float* __restrict__ A, const float* __restrict__ B,
    const float* __restrict__ bias, float* __restrict__ C,
    int M, int K, int Nout, int relu)
{
    __shared__ __align__(16) float As[2][BK][BM + 4];
    __shared__ __align__(16) float Bs[2][BK][BN];

    const int tid  = threadIdx.x;
    const int tcol = tid & 15;
    const int trow = tid >> 4;
    const int blockRow = blockIdx.x * BM;
    const int blockCol = blockIdx.y * BN;

    float acc[TM][TN];
#pragma unroll
    for (int i = 0; i < TM; i++)
#pragma unroll
        for (int j = 0; j < TN; j++) acc[i][j] = 0.f;

    const int a_row = tid & 127;
    const int a_kq0 = tid >> 7;
    const int a_grow = blockRow + a_row;
    const bool a_ok = (a_grow < M);
    const int b_row = tid >> 4;
    const int b_cq  = tid & 15;

    float4 a_reg[2], b_reg;

#pragma unroll
    for (int p = 0; p < 2; p++) {
        int kq = a_kq0 + p * 2;
        a_reg[p] = a_ok ? *(const float4*)(A + (size_t)a_grow * K + kq * 4)
                        : make_float4(0.f, 0.f, 0.f, 0.f);
    }
    b_reg = *(const float4*)(B + (size_t)b_row * Nout + blockCol + b_cq * 4);

#pragma unroll
    for (int p = 0; p < 2; p++) {
        int kq = a_kq0 + p * 2;
        As[0][kq * 4 + 0][a_row] = a_reg[p].x;
        As[0][kq * 4 + 1][a_row] = a_reg[p].y;
        As[0][kq * 4 + 2][a_row] = a_reg[p].z;
        As[0][kq * 4 + 3][a_row] = a_reg[p].w;
    }
    *(float4*)&Bs[0][b_row][b_cq * 4] = b_reg;
    __syncthreads();

    int buf = 0;
    for (int k0 = BK; k0 < K; k0 += BK) {
#pragma unroll
        for (int p = 0; p < 2; p++) {
            int kq = a_kq0 + p * 2;
            a_reg[p] = a_ok ? *(const float4*)(A + (size_t)a_grow * K + k0 + kq * 4)
                            : make_float4(0.f, 0.f, 0.f, 0.f);
        }
        b_reg = *(const float4*)(B + (size_t)(k0 + b_row) * Nout + blockCol + b_cq * 4);

#pragma unroll
        for (int kk = 0; kk < BK; kk++) {
            const float4* ap = (const float4*)&As[buf][kk][trow * TM];
            float4 a0 = ap[0], a1 = ap[1];
            float4 b  = *(const float4*)&Bs[buf][kk][tcol * TN];
            float a[TM] = {a0.x, a0.y, a0.z, a0.w, a1.x, a1.y, a1.z, a1.w};
            float bb[TN] = {b.x, b.y, b.z, b.w};
#pragma unroll
            for (int i = 0; i < TM; i++)
#pragma unroll
                for (int j = 0; j < TN; j++)
                    acc[i][j] = fmaf(a[i], bb[j], acc[i][j]);
        }

#pragma unroll
        for (int p = 0; p < 2; p++) {
            int kq = a_kq0 + p * 2;
            As[buf ^ 1][kq * 4 + 0][a_row] = a_reg[p].x;
            As[buf ^ 1][kq * 4 + 1][a_row] = a_reg[p].y;
            As[buf ^ 1][kq * 4 + 2][a_row] = a_reg[p].z;
            As[buf ^ 1][kq * 4 + 3][a_row] = a_reg[p].w;
        }
        *(float4*)&Bs[buf ^ 1][b_row][b_cq * 4] = b_reg;
        __syncthreads();
        buf ^= 1;
    }

#pragma unroll
    for (int kk = 0; kk < BK; kk++) {
        const float4* ap = (const float4*)&As[buf][kk][trow * TM];
        float4 a0 = ap[0], a1 = ap[1];
        float4 b  = *(const float4*)&Bs[buf][kk][tcol * TN];
        float a[TM] = {a0.x, a0.y, a0.z, a0.w, a1.x, a1.y, a1.z, a1.w};
        float bb[TN] = {b.x, b.y, b.z, b.w};
#pragma unroll
        for (int i = 0; i < TM; i++)
#pragma unroll
            for (int j = 0; j < TN; j++)
                acc[i][j] = fmaf(a[i], bb[j], acc[i][j]);
    }

    float4 bv = *(const float4*)(bias + blockCol + tcol * TN);
#pragma unroll
    for (int i = 0; i < TM; i++) {
        int grow = blockRow + trow * TM + i;
        if (grow >= M) continue;
        float4 v;
        v.x = acc[i][0] + bv.x;
        v.y = acc[i][1] + bv.y;
        v.z = acc[i][2] + bv.z;
        v.w = acc[i][3] + bv.w;
        if (relu) {
            v.x = fmaxf(v.x, 0.f); v.y = fmaxf(v.y, 0.f);
            v.z = fmaxf(v.z, 0.f); v.w = fmaxf(v.w, 0.f);
        }
        *(float4*)(C + (size_t)grow * Nout + blockCol + tcol * TN) = v;
    }
}

// ---------------------------------------------------------------------------
// CSR build: histogram -> scan -> fill (edges sorted by dst)
// ---------------------------------------------------------------------------
__global__ void deg_count(const int* __restrict__ dst, int* __restrict__ rowptr, int E)
{
    int e = blockIdx.x * blockDim.x + threadIdx.x;
    if (e < E) atomicAdd(&rowptr[dst[e] + 1], 1);
}

// inclusive scan of arr[0..n) in blocks of 1024; per-block totals to bsum
__global__ __launch_bounds__(1024) void scan1(int* __restrict__ arr,
                                              int* __restrict__ bsum, int n)
{
    __shared__ int s[1024];
    int tid = threadIdx.x;
    int i = blockIdx.x * 1024 + tid;
    int v = (i < n) ? arr[i] : 0;
    s[tid] = v;
    __syncthreads();
#pragma unroll
    for (int off = 1; off < 1024; off <<= 1) {
        int t = (tid >= off) ? s[tid - off] : 0;
        __syncthreads();
        s[tid] += t;
        __syncthreads();
    }
    if (i < n) arr[i] = s[tid];
    if (tid == 1023) bsum[blockIdx.x] = s[1023];
}

__global__ void scan2(int* __restrict__ bsum, int nb)
{
    if (threadIdx.x == 0 && blockIdx.x == 0) {
        int run = 0;
        for (int i = 0; i < nb; i++) { int v = bsum[i]; bsum[i] = run; run += v; }
    }
}

__global__ __launch_bounds__(1024) void scan3(int* __restrict__ arr,
                                              const int* __restrict__ bsum, int n)
{
    int i = blockIdx.x * 1024 + threadIdx.x;
    if (i < n) arr[i] += bsum[blockIdx.x];
}

__global__ void fin_deg(const int* __restrict__ rowptr, float* __restrict__ dinv,
                        int* __restrict__ cursor, int n)
{
    int i = blockIdx.x * blockDim.x + threadIdx.x;
    if (i < n) {
        int beg = rowptr[i];
        int deg = rowptr[i + 1] - beg;
        dinv[i] = rsqrtf((float)deg + 1.0f);   // +1 self-loop
        cursor[i] = beg;
    }
}

__global__ void fill_csr(const int* __restrict__ src, const int* __restrict__ dst,
                         const float* __restrict__ dinv, int* __restrict__ cursor,
                         int* __restrict__ csr_src, float* __restrict__ csr_norm, int E)
{
    int e = blockIdx.x * blockDim.x + threadIdx.x;
    if (e >= E) return;
    int s = src[e];
    int d = dst[e];
    int pos = atomicAdd(&cursor[d], 1);
    csr_src[pos] = s;
    csr_norm[pos] = dinv[s] * dinv[d];
}

// ---------------------------------------------------------------------------
// Gather aggregation: y[node] = relu( sum_{e in CSR[node]} h[src_e]*norm_e
//                                     + h[node]*dinv[node]^2 )
// One warp per node; lane owns 4 features (H=128 = 32 lanes x float4).
// ---------------------------------------------------------------------------
__global__ __launch_bounds__(256) void gather_conv(
    const float* __restrict__ h, const int* __restrict__ csr_src,
    const float* __restrict__ csr_norm, const int* __restrict__ rowptr,
    const float* __restrict__ dinv, float* __restrict__ y, int N)
{
    int node = blockIdx.x * 8 + (threadIdx.x >> 5);
    if (node >= N) return;
    int lane = threadIdx.x & 31;

    int beg = rowptr[node];
    int end = rowptr[node + 1];
    float di = dinv[node];
    float w = di * di;

    float4 self = *(const float4*)(h + (size_t)node * HH + lane * 4);
    float4 acc;
    acc.x = self.x * w; acc.y = self.y * w;
    acc.z = self.z * w; acc.w = self.w * w;

    for (int e = beg; e < end; e++) {
        int s = __ldg(csr_src + e);
        float nm = __ldg(csr_norm + e);
        float4 v = *(const float4*)(h + (size_t)s * HH + lane * 4);
        acc.x = fmaf(v.x, nm, acc.x);
        acc.y = fmaf(v.y, nm, acc.y);
        acc.z = fmaf(v.z, nm, acc.z);
        acc.w = fmaf(v.w, nm, acc.w);
    }
    acc.x = fmaxf(acc.x, 0.f);
    acc.y = fmaxf(acc.y, 0.f);
    acc.z = fmaxf(acc.z, 0.f);
    acc.w = fmaxf(acc.w, 0.f);
    *(float4*)(y + (size_t)node * HH + lane * 4) = acc;
}

// ---------------------------------------------------------------------------
// log_softmax over C=64 classes; 1 warp per row, 2 classes per lane.
// ---------------------------------------------------------------------------
__global__ void log_softmax_k(const float* __restrict__ logits, float* __restrict__ out, int N)
{
    int row = blockIdx.x * blockDim.y + threadIdx.y;
    if (row >= N) return;
    int lane = threadIdx.x;
    const float* lr = logits + (size_t)row * CC;
    float v0 = lr[lane], v1 = lr[lane + 32];
    float m = fmaxf(v0, v1);
#pragma unroll
    for (int o = 16; o; o >>= 1) m = fmaxf(m, __shfl_xor_sync(0xffffffffu, m, o));
    float s = expf(v0 - m) + expf(v1 - m);
#pragma unroll
    for (int o = 16; o; o >>= 1) s += __shfl_xor_sync(0xffffffffu, s, o);
    float ls = m + logf(s);
    float* orow = out + (size_t)row * CC;
    orow[lane] = v0 - ls;
    orow[lane + 32] = v1 - ls;
}

// ---------------------------------------------------------------------------
// Launch
// ---------------------------------------------------------------------------
extern "C" void kernel_launch(void* const* d_in, const int* in_sizes, int n_in,
                              void* d_out, int out_size)
{
    const float* x     = (const float*)d_in[0];
    const int*   ei    = (const int*)d_in[1];
    const float* W0    = (const float*)d_in[2];
    const float* b0    = (const float*)d_in[3];
    const float* W1    = (const float*)d_in[4];
    const float* b1    = (const float*)d_in[5];
    const float* W2    = (const float*)d_in[6];
    const float* b2    = (const float*)d_in[7];
    const float* fc1_w = (const float*)d_in[8];
    const float* fc1_b = (const float*)d_in[9];
    const float* fc2_w = (const float*)d_in[10];
    const float* fc2_b = (const float*)d_in[11];
    const float* fc3_w = (const float*)d_in[12];
    const float* fc3_b = (const float*)d_in[13];

    const int N = in_sizes[0] / FIN;   // 100000
    const int E = in_sizes[1] / 2;     // 1600000
    const int* src = ei;
    const int* dst = ei + E;

    float *h_, *y_, *dinv_, *csr_norm_;
    int *rowptr_, *cursor_, *csr_src_, *bsum_;
    cudaGetSymbolAddress((void**)&h_,        g_h);
    cudaGetSymbolAddress((void**)&y_,        g_y);
    cudaGetSymbolAddress((void**)&dinv_,     g_dinv);
    cudaGetSymbolAddress((void**)&rowptr_,   g_rowptr);
    cudaGetSymbolAddress((void**)&cursor_,   g_cursor);
    cudaGetSymbolAddress((void**)&csr_src_,  g_csr_src);
    cudaGetSymbolAddress((void**)&csr_norm_, g_csr_norm);
    cudaGetSymbolAddress((void**)&bsum_,     g_bsum);

    const int T = 256;
    dim3 gemm_grid((N + BM - 1) / BM, HH / BN);     // 782 x 2
    dim3 gemm_grid_c((N + BM - 1) / BM, CC / BN);   // 782 x 1

    // ---- CSR build + normalization ----
    const int np1 = N + 1;
    const int nb = (np1 + 1023) / 1024;
    cudaMemsetAsync(rowptr_, 0, (size_t)np1 * sizeof(int));
    deg_count<<<(E + T - 1) / T, T>>>(dst, rowptr_, E);
    scan1<<<nb, 1024>>>(rowptr_, bsum_, np1);
    scan2<<<1, 32>>>(bsum_, nb);
    scan3<<<nb, 1024>>>(rowptr_, bsum_, np1);
    fin_deg<<<(N + T - 1) / T, T>>>(rowptr_, dinv_, cursor_, N);
    fill_csr<<<(E + T - 1) / T, T>>>(src, dst, dinv_, cursor_, csr_src_, csr_norm_, E);

    const int gather_blocks = (N + 7) / 8;

    // ---- conv0 ----
    sgemm_bias<<<gemm_grid, T>>>(x, W0, b0, h_, N, FIN, HH, 0);
    gather_conv<<<gather_blocks, T>>>(h_, csr_src_, csr_norm_, rowptr_, dinv_, y_, N);

    // ---- conv1 ----
    sgemm_bias<<<gemm_grid, T>>>(y_, W1, b1, h_, N, HH, HH, 0);
    gather_conv<<<gather_blocks, T>>>(h_, csr_src_, csr_norm_, rowptr_, dinv_, y_, N);

    // ---- conv2 ----
    sgemm_bias<<<gemm_grid, T>>>(y_, W2, b2, h_, N, HH, HH, 0);
    gather_conv<<<gather_blocks, T>>>(h_, csr_src_, csr_norm_, rowptr_, dinv_, y_, N);

    // ---- MLP ----
    sgemm_bias<<<gemm_grid, T>>>(y_, fc1_w, fc1_b, h_, N, HH, HH, 1);
    sgemm_bias<<<gemm_grid, T>>>(h_, fc2_w, fc2_b, y_, N, HH, HH, 1);
    sgemm_bias<<<gemm_grid_c, T>>>(y_, fc3_w, fc3_b, h_, N, HH, CC, 0);

    // ---- log_softmax ----
    dim3 ls_block(32, 8);
    log_softmax_k<<<(N + 7) / 8, ls_block>>>(h_, (float*)d_out, N);
}

// round 8
// speedup vs baseline: 2.6029x; 1.6803x over previous
#include <cuda_runtime.h>
#include <cuda_bf16.h>
#include <math.h>
#include <stdint.h>

// Problem constants (fixed by reference)
constexpr int NN  = 100000;
constexpr int EE  = 1600000;
constexpr int FIN = 512;
constexpr int HH  = 128;
constexpr int CC  = 64;

// Scratch (device globals: allocation-free rule)
__device__ float g_h[(size_t)NN * HH];
__device__ float g_y[(size_t)NN * HH];
__device__ float g_dinv[NN];
__device__ int   g_rowptr[NN + 1];
__device__ int   g_cursor[NN];
__device__ int   g_csr_src[EE];
__device__ float g_csr_norm[EE];
__device__ int   g_bsum[256];
__device__ __nv_bfloat16 g_bthi[(size_t)HH * FIN];  // W^T hi, [N x K] max 128x512
__device__ __nv_bfloat16 g_btlo[(size_t)HH * FIN];  // W^T lo

// ---------------------------------------------------------------------------
// mma.sync bf16 helpers (baseline PTX ISA; compiles for compute_103)
// ---------------------------------------------------------------------------
__device__ __forceinline__ uint32_t sptr(const void* p) {
    return (uint32_t)__cvta_generic_to_shared(p);
}
__device__ __forceinline__ void ldm4(uint32_t* r, uint32_t addr) {
    asm volatile("ldmatrix.sync.aligned.m8n8.x4.shared.b16 {%0,%1,%2,%3}, [%4];"
                 : "=r"(r[0]), "=r"(r[1]), "=r"(r[2]), "=r"(r[3]) : "r"(addr));
}
__device__ __forceinline__ void mma16816(float* c, const uint32_t* a, const uint32_t* b) {
    asm volatile(
        "mma.sync.aligned.m16n8k16.row.col.f32.bf16.bf16.f32 "
        "{%0,%1,%2,%3}, {%4,%5,%6,%7}, {%8,%9}, {%0,%1,%2,%3};"
        : "+f"(c[0]), "+f"(c[1]), "+f"(c[2]), "+f"(c[3])
        : "r"(a[0]), "r"(a[1]), "r"(a[2]), "r"(a[3]), "r"(b[0]), "r"(b[1]));
}

// ---------------------------------------------------------------------------
// bf16 3-term split GEMM: C[M x BN_] = A[M x K] @ W + bias (+relu).
// A split to bf16 hi/lo in-kernel; Bt_hi/Bt_lo = W^T pre-split [BN_ x K].
// CTA: 128 rows x BN_ cols, 256 threads (8 warps), warp tile 32 x (BN_/2).
// ---------------------------------------------------------------------------
#define APITCH 40   // smem pitch in halves (80B: 5x16B phases, coprime with 8)

template <int BN_>
__global__ __launch_bounds__(256) void bf16_gemm(
    const float* __restrict__ A,
    const __nv_bfloat16* __restrict__ Bt_hi,
    const __nv_bfloat16* __restrict__ Bt_lo,
    const float* __restrict__ bias, float* __restrict__ C,
    int M, int K, int relu)
{
    constexpr int NF = BN_ / 16;             // n8 frags per warp (8 or 4)
    __shared__ __align__(16) __nv_bfloat16 Ahi_s[128][APITCH];
    __shared__ __align__(16) __nv_bfloat16 Alo_s[128][APITCH];
    __shared__ __align__(16) __nv_bfloat16 Bhi_s[BN_][APITCH];
    __shared__ __align__(16) __nv_bfloat16 Blo_s[BN_][APITCH];

    const int tid  = threadIdx.x;
    const int wid  = tid >> 5;
    const int lane = tid & 31;
    const int warp_m = wid & 3;              // 4 groups x 32 rows
    const int warp_n = wid >> 2;             // 2 groups x BN_/2 cols
    const int blockRow = blockIdx.x * 128;

    float acc[2][NF][4];
#pragma unroll
    for (int i = 0; i < 2; i++)
#pragma unroll
        for (int j = 0; j < NF; j++)
#pragma unroll
            for (int q = 0; q < 4; q++) acc[i][j][q] = 0.f;

    for (int k0 = 0; k0 < K; k0 += 32) {
        // ---- load A 128x32 fp32, split to bf16 hi/lo in smem ----
#pragma unroll
        for (int p = 0; p < 4; p++) {
            int v = p * 256 + tid;
            int r = v >> 3;
            int cq = (v & 7) * 4;
            int grow = blockRow + r;
            float4 x = make_float4(0.f, 0.f, 0.f, 0.f);
            if (grow < M) x = *(const float4*)(A + (size_t)grow * K + k0 + cq);
            __nv_bfloat16 h0 = __float2bfloat16_rn(x.x);
            __nv_bfloat16 h1 = __float2bfloat16_rn(x.y);
            __nv_bfloat16 h2 = __float2bfloat16_rn(x.z);
            __nv_bfloat16 h3 = __float2bfloat16_rn(x.w);
            __nv_bfloat16 l0 = __float2bfloat16_rn(x.x - __bfloat162float(h0));
            __nv_bfloat16 l1 = __float2bfloat16_rn(x.y - __bfloat162float(h1));
            __nv_bfloat16 l2 = __float2bfloat16_rn(x.z - __bfloat162float(h2));
            __nv_bfloat16 l3 = __float2bfloat16_rn(x.w - __bfloat162float(h3));
            *(__nv_bfloat162*)&Ahi_s[r][cq]     = __halves2bfloat162(h0, h1);
            *(__nv_bfloat162*)&Ahi_s[r][cq + 2] = __halves2bfloat162(h2, h3);
            *(__nv_bfloat162*)&Alo_s[r][cq]     = __halves2bfloat162(l0, l1);
            *(__nv_bfloat162*)&Alo_s[r][cq + 2] = __halves2bfloat162(l2, l3);
        }
        // ---- load B tiles (pre-split bf16) ----
#pragma unroll
        for (int p = 0; p < BN_ / 64; p++) {
            int v = p * 256 + tid;
            int n = v >> 2;
            int kc = (v & 3) * 8;
            *(uint4*)&Bhi_s[n][kc] = *(const uint4*)(Bt_hi + (size_t)n * K + k0 + kc);
            *(uint4*)&Blo_s[n][kc] = *(const uint4*)(Bt_lo + (size_t)n * K + k0 + kc);
        }
        __syncthreads();

#pragma unroll
        for (int kk = 0; kk < 32; kk += 16) {
            // A fragments: 2 m16 frags x {hi,lo}
            uint32_t aH[2][4], aL[2][4];
            {
                int row = warp_m * 32 + (lane & 15);
                int col = kk + ((lane >> 4) << 3);
#pragma unroll
                for (int fm = 0; fm < 2; fm++) {
                    ldm4(aH[fm], sptr(&Ahi_s[row + fm * 16][col]));
                    ldm4(aL[fm], sptr(&Alo_s[row + fm * 16][col]));
                }
            }
            // B fragments: NF n8 frags x {hi,lo}, loaded as x4 pairs
            uint32_t bH[NF][2], bL[NF][2];
            {
                int rbase = warp_n * (NF * 8) + (lane & 7) + ((lane >> 4) << 3);
                int col = kk + ((lane >> 3) & 1) * 8;
#pragma unroll
                for (int fp = 0; fp < NF / 2; fp++) {
                    uint32_t t[4];
                    ldm4(t, sptr(&Bhi_s[rbase + fp * 16][col]));
                    bH[fp * 2][0] = t[0]; bH[fp * 2][1] = t[1];
                    bH[fp * 2 + 1][0] = t[2]; bH[fp * 2 + 1][1] = t[3];
                    ldm4(t, sptr(&Blo_s[rbase + fp * 16][col]));
                    bL[fp * 2][0] = t[0]; bL[fp * 2][1] = t[1];
                    bL[fp * 2 + 1][0] = t[2]; bL[fp * 2 + 1][1] = t[3];
                }
            }
#pragma unroll
            for (int fm = 0; fm < 2; fm++)
#pragma unroll
                for (int fn = 0; fn < NF; fn++) {
                    mma16816(acc[fm][fn], aH[fm], bH[fn]);
                    mma16816(acc[fm][fn], aH[fm], bL[fn]);
                    mma16816(acc[fm][fn], aL[fm], bH[fn]);
                }
        }
        __syncthreads();
    }

    // ---- epilogue: bias (+relu), float2 stores ----
#pragma unroll
    for (int fm = 0; fm < 2; fm++) {
#pragma unroll
        for (int fn = 0; fn < NF; fn++) {
            int gn = warp_n * (NF * 8) + fn * 8 + (lane & 3) * 2;
            float2 bv = *(const float2*)(bias + gn);
            int gm0 = blockRow + warp_m * 32 + fm * 16 + (lane >> 2);
            float2 v0, v1;
            v0.x = acc[fm][fn][0] + bv.x;
            v0.y = acc[fm][fn][1] + bv.y;
            v1.x = acc[fm][fn][2] + bv.x;
            v1.y = acc[fm][fn][3] + bv.y;
            if (relu) {
                v0.x = fmaxf(v0.x, 0.f); v0.y = fmaxf(v0.y, 0.f);
                v1.x = fmaxf(v1.x, 0.f); v1.y = fmaxf(v1.y, 0.f);
            }
            if (gm0 < M)     *(float2*)(C + (size_t)gm0 * BN_ + gn) = v0;
            if (gm0 + 8 < M) *(float2*)(C + (size_t)(gm0 + 8) * BN_ + gn) = v1;
        }
    }
}

// Weight transpose + bf16 hi/lo split: Bt[n*K+k] = split(W[k*N+n])
__global__ void wsplit(const float* __restrict__ w, __nv_bfloat16* __restrict__ bthi,
                       __nv_bfloat16* __restrict__ btlo, int K, int Nout)
{
    int i = blockIdx.x * blockDim.x + threadIdx.x;
    if (i >= K * Nout) return;
    int k = i / Nout, n = i % Nout;
    float v = w[i];
    __nv_bfloat16 h = __float2bfloat16_rn(v);
    bthi[(size_t)n * K + k] = h;
    btlo[(size_t)n * K + k] = __float2bfloat16_rn(v - __bfloat162float(h));
}

// ---------------------------------------------------------------------------
// CSR build: histogram -> scan -> fill (edges sorted by dst)
// ---------------------------------------------------------------------------
__global__ void deg_count(const int* __restrict__ dst, int* __restrict__ rowptr, int E)
{
    int e = blockIdx.x * blockDim.x + threadIdx.x;
    if (e < E) atomicAdd(&rowptr[dst[e] + 1], 1);
}

__global__ __launch_bounds__(1024) void scan1(int* __restrict__ arr,
                                              int* __restrict__ bsum, int n)
{
    __shared__ int s[1024];
    int tid = threadIdx.x;
    int i = blockIdx.x * 1024 + tid;
    int v = (i < n) ? arr[i] : 0;
    s[tid] = v;
    __syncthreads();
#pragma unroll
    for (int off = 1; off < 1024; off <<= 1) {
        int t = (tid >= off) ? s[tid - off] : 0;
        __syncthreads();
        s[tid] += t;
        __syncthreads();
    }
    if (i < n) arr[i] = s[tid];
    if (tid == 1023) bsum[blockIdx.x] = s[1023];
}

__global__ void scan2(int* __restrict__ bsum, int nb)
{
    if (threadIdx.x == 0 && blockIdx.x == 0) {
        int run = 0;
        for (int i = 0; i < nb; i++) { int v = bsum[i]; bsum[i] = run; run += v; }
    }
}

__global__ __launch_bounds__(1024) void scan3(int* __restrict__ arr,
                                              const int* __restrict__ bsum, int n)
{
    int i = blockIdx.x * 1024 + threadIdx.x;
    if (i < n) arr[i] += bsum[blockIdx.x];
}

__global__ void fin_deg(const int* __restrict__ rowptr, float* __restrict__ dinv,
                        int* __restrict__ cursor, int n)
{
    int i = blockIdx.x * blockDim.x + threadIdx.x;
    if (i < n) {
        int beg = rowptr[i];
        int deg = rowptr[i + 1] - beg;
        dinv[i] = rsqrtf((float)deg + 1.0f);
        cursor[i] = beg;
    }
}

__global__ void fill_csr(const int* __restrict__ src, const int* __restrict__ dst,
                         const float* __restrict__ dinv, int* __restrict__ cursor,
                         int* __restrict__ csr_src, float* __restrict__ csr_norm, int E)
{
    int e = blockIdx.x * blockDim.x + threadIdx.x;
    if (e >= E) return;
    int s = src[e];
    int d = dst[e];
    int pos = atomicAdd(&cursor[d], 1);
    csr_src[pos] = s;
    csr_norm[pos] = dinv[s] * dinv[d];
}

// ---------------------------------------------------------------------------
// Gather aggregation: y[node] = relu(sum_e h[src_e]*norm_e + h[node]*dinv^2)
// ---------------------------------------------------------------------------
__global__ __launch_bounds__(256) void gather_conv(
    const float* __restrict__ h, const int* __restrict__ csr_src,
    const float* __restrict__ csr_norm, const int* __restrict__ rowptr,
    const float* __restrict__ dinv, float* __restrict__ y, int N)
{
    int node = blockIdx.x * 8 + (threadIdx.x >> 5);
    if (node >= N) return;
    int lane = threadIdx.x & 31;

    int beg = rowptr[node];
    int end = rowptr[node + 1];
    float di = dinv[node];
    float w = di * di;

    float4 self = *(const float4*)(h + (size_t)node * HH + lane * 4);
    float4 acc;
    acc.x = self.x * w; acc.y = self.y * w;
    acc.z = self.z * w; acc.w = self.w * w;

    for (int e = beg; e < end; e++) {
        int s = __ldg(csr_src + e);
        float nm = __ldg(csr_norm + e);
        float4 v = *(const float4*)(h + (size_t)s * HH + lane * 4);
        acc.x = fmaf(v.x, nm, acc.x);
        acc.y = fmaf(v.y, nm, acc.y);
        acc.z = fmaf(v.z, nm, acc.z);
        acc.w = fmaf(v.w, nm, acc.w);
    }
    acc.x = fmaxf(acc.x, 0.f);
    acc.y = fmaxf(acc.y, 0.f);
    acc.z = fmaxf(acc.z, 0.f);
    acc.w = fmaxf(acc.w, 0.f);
    *(float4*)(y + (size_t)node * HH + lane * 4) = acc;
}

// ---------------------------------------------------------------------------
// log_softmax over C=64 classes; 1 warp per row, 2 classes per lane.
// ---------------------------------------------------------------------------
__global__ void log_softmax_k(const float* __restrict__ logits, float* __restrict__ out, int N)
{
    int row = blockIdx.x * blockDim.y + threadIdx.y;
    if (row >= N) return;
    int lane = threadIdx.x;
    const float* lr = logits + (size_t)row * CC;
    float v0 = lr[lane], v1 = lr[lane + 32];
    float m = fmaxf(v0, v1);
#pragma unroll
    for (int o = 16; o; o >>= 1) m = fmaxf(m, __shfl_xor_sync(0xffffffffu, m, o));
    float s = expf(v0 - m) + expf(v1 - m);
#pragma unroll
    for (int o = 16; o; o >>= 1) s += __shfl_xor_sync(0xffffffffu, s, o);
    float ls = m + logf(s);
    float* orow = out + (size_t)row * CC;
    orow[lane] = v0 - ls;
    orow[lane + 32] = v1 - ls;
}

// ---------------------------------------------------------------------------
// Launch
// ---------------------------------------------------------------------------
extern "C" void kernel_launch(void* const* d_in, const int* in_sizes, int n_in,
                              void* d_out, int out_size)
{
    const float* x     = (const float*)d_in[0];
    const int*   ei    = (const int*)d_in[1];
    const float* W0    = (const float*)d_in[2];
    const float* b0    = (const float*)d_in[3];
    const float* W1    = (const float*)d_in[4];
    const float* b1    = (const float*)d_in[5];
    const float* W2    = (const float*)d_in[6];
    const float* b2    = (const float*)d_in[7];
    const float* fc1_w = (const float*)d_in[8];
    const float* fc1_b = (const float*)d_in[9];
    const float* fc2_w = (const float*)d_in[10];
    const float* fc2_b = (const float*)d_in[11];
    const float* fc3_w = (const float*)d_in[12];
    const float* fc3_b = (const float*)d_in[13];

    const int N = in_sizes[0] / FIN;   // 100000
    const int E = in_sizes[1] / 2;     // 1600000
    const int* src = ei;
    const int* dst = ei + E;

    float *h_, *y_, *dinv_, *csr_norm_;
    int *rowptr_, *cursor_, *csr_src_, *bsum_;
    __nv_bfloat16 *bthi_, *btlo_;
    cudaGetSymbolAddress((void**)&h_,        g_h);
    cudaGetSymbolAddress((void**)&y_,        g_y);
    cudaGetSymbolAddress((void**)&dinv_,     g_dinv);
    cudaGetSymbolAddress((void**)&rowptr_,   g_rowptr);
    cudaGetSymbolAddress((void**)&cursor_,   g_cursor);
    cudaGetSymbolAddress((void**)&csr_src_,  g_csr_src);
    cudaGetSymbolAddress((void**)&csr_norm_, g_csr_norm);
    cudaGetSymbolAddress((void**)&bsum_,     g_bsum);
    cudaGetSymbolAddress((void**)&bthi_,     g_bthi);
    cudaGetSymbolAddress((void**)&btlo_,     g_btlo);

    const int T = 256;
    const int gemm_blocks = (N + 127) / 128;   // 782

    // ---- CSR build + normalization ----
    const int np1 = N + 1;
    const int nb = (np1 + 1023) / 1024;
    cudaMemsetAsync(rowptr_, 0, (size_t)np1 * sizeof(int));
    deg_count<<<(E + T - 1) / T, T>>>(dst, rowptr_, E);
    scan1<<<nb, 1024>>>(rowptr_, bsum_, np1);
    scan2<<<1, 32>>>(bsum_, nb);
    scan3<<<nb, 1024>>>(rowptr_, bsum_, np1);
    fin_deg<<<(N + T - 1) / T, T>>>(rowptr_, dinv_, cursor_, N);
    fill_csr<<<(E + T - 1) / T, T>>>(src, dst, dinv_, cursor_, csr_src_, csr_norm_, E);

    const int gather_blocks = (N + 7) / 8;

    // ---- conv0 ----
    wsplit<<<(FIN * HH + T - 1) / T, T>>>(W0, bthi_, btlo_, FIN, HH);
    bf16_gemm<128><<<gemm_blocks, T>>>(x, bthi_, btlo_, b0, h_, N, FIN, 0);
    gather_conv<<<gather_blocks, T>>>(h_, csr_src_, csr_norm_, rowptr_, dinv_, y_, N);

    // ---- conv1 ----
    wsplit<<<(HH * HH + T - 1) / T, T>>>(W1, bthi_, btlo_, HH, HH);
    bf16_gemm<128><<<gemm_blocks, T>>>(y_, bthi_, btlo_, b1, h_, N, HH, 0);
    gather_conv<<<gather_blocks, T>>>(h_, csr_src_, csr_norm_, rowptr_, dinv_, y_, N);

    // ---- conv2 ----
    wsplit<<<(HH * HH + T - 1) / T, T>>>(W2, bthi_, btlo_, HH, HH);
    bf16_gemm<128><<<gemm_blocks, T>>>(y_, bthi_, btlo_, b2, h_, N, HH, 0);
    gather_conv<<<gather_blocks, T>>>(h_, csr_src_, csr_norm_, rowptr_, dinv_, y_, N);

    // ---- MLP ----
    wsplit<<<(HH * HH + T - 1) / T, T>>>(fc1_w, bthi_, btlo_, HH, HH);
    bf16_gemm<128><<<gemm_blocks, T>>>(y_, bthi_, btlo_, fc1_b, h_, N, HH, 1);
    wsplit<<<(HH * HH + T - 1) / T, T>>>(fc2_w, bthi_, btlo_, HH, HH);
    bf16_gemm<128><<<gemm_blocks, T>>>(h_, bthi_, btlo_, fc2_b, y_, N, HH, 1);
    wsplit<<<(HH * CC + T - 1) / T, T>>>(fc3_w, bthi_, btlo_, HH, CC);
    bf16_gemm<64><<<gemm_blocks, T>>>(y_, bthi_, btlo_, fc3_b, h_, N, HH, 0);

    // ---- log_softmax ----
    dim3 ls_block(32, 8);
    log_softmax_k<<<(N + 7) / 8, ls_block>>>(h_, (float*)d_out, N);
}

// round 12
// speedup vs baseline: 2.6451x; 1.0162x over previous
#include <cuda_runtime.h>
#include <cuda_bf16.h>
#include <math.h>
#include <stdint.h>

// Problem constants (fixed by reference)
constexpr int NN  = 100000;
constexpr int EE  = 1600000;
constexpr int FIN = 512;
constexpr int HH  = 128;
constexpr int CC  = 64;

// Packed transposed/split weight buffer segment bases (elements)
constexpr int WOFF_W0  = 0;         // 512x128
constexpr int WOFF_W1  = 65536;     // 128x128
constexpr int WOFF_W2  = 81920;
constexpr int WOFF_FC1 = 98304;
constexpr int WOFF_FC2 = 114688;
constexpr int WOFF_FC3 = 131072;    // 128x64
constexpr int WTOT     = 139264;

// Scratch (device globals: allocation-free rule)
__device__ float g_h[(size_t)NN * HH];
__device__ float g_y[(size_t)NN * HH];
__device__ float g_dinv[NN];
__device__ int   g_rowptr[NN + 1];
__device__ int   g_cursor[NN];
__device__ int   g_csr_src[EE];
__device__ float g_csr_norm[EE];
__device__ int   g_bsum[256];
__device__ __nv_bfloat16 g_wthi[WTOT];
__device__ __nv_bfloat16 g_wtlo[WTOT];

// ---------------------------------------------------------------------------
// PTX helpers (baseline ISA; compiles for compute_103)
// ---------------------------------------------------------------------------
__device__ __forceinline__ uint32_t sptr(const void* p) {
    return (uint32_t)__cvta_generic_to_shared(p);
}
__device__ __forceinline__ void ldm4(uint32_t* r, uint32_t addr) {
    asm volatile("ldmatrix.sync.aligned.m8n8.x4.shared.b16 {%0,%1,%2,%3}, [%4];"
                 : "=r"(r[0]), "=r"(r[1]), "=r"(r[2]), "=r"(r[3]) : "r"(addr));
}
__device__ __forceinline__ void mma16816(float* c, const uint32_t* a, const uint32_t* b) {
    asm volatile(
        "mma.sync.aligned.m16n8k16.row.col.f32.bf16.bf16.f32 "
        "{%0,%1,%2,%3}, {%4,%5,%6,%7}, {%8,%9}, {%0,%1,%2,%3};"
        : "+f"(c[0]), "+f"(c[1]), "+f"(c[2]), "+f"(c[3])
        : "r"(a[0]), "r"(a[1]), "r"(a[2]), "r"(a[3]), "r"(b[0]), "r"(b[1]));
}
__device__ __forceinline__ void cp16(uint32_t saddr, const void* gaddr) {
    asm volatile("cp.async.ca.shared.global [%0], [%1], 16;"
                 :: "r"(saddr), "l"(gaddr) : "memory");
}
__device__ __forceinline__ void cp_commit() {
    asm volatile("cp.async.commit_group;" ::: "memory");
}
__device__ __forceinline__ void cp_wait0() {
    asm volatile("cp.async.wait_group 0;" ::: "memory");
}

// ---------------------------------------------------------------------------
// bf16 3-term split GEMM, software-pipelined:
//   C[M x BN_] = A[M x K] @ W + bias (+relu)
// A: fp32, split to bf16 hi/lo in-kernel (register-prefetched).
// Bt_hi/Bt_lo: W^T pre-split [BN_ x K], loaded via cp.async.
// CTA: 128 rows, 256 threads (8 warps), warp tile 32 x (BN_/2).
// ---------------------------------------------------------------------------
#define APITCH 40   // smem pitch in halves (80B; breaks ldmatrix bank conflicts)

template <int BN_>
__global__ __launch_bounds__(256, 2) void bf16_gemm(
    const float* __restrict__ A,
    const __nv_bfloat16* __restrict__ Bt_hi,
    const __nv_bfloat16* __restrict__ Bt_lo,
    const float* __restrict__ bias, float* __restrict__ C,
    int M, int K, int relu)
{
    constexpr int NF = BN_ / 16;
    constexpr int A_EL  = 128 * APITCH;
    constexpr int B_EL  = BN_ * APITCH;
    constexpr int BUF_EL = 2 * A_EL + 2 * B_EL;
    extern __shared__ __align__(16) __nv_bfloat16 sm[];

    const int tid  = threadIdx.x;
    const int wid  = tid >> 5;
    const int lane = tid & 31;
    const int warp_m = wid & 3;
    const int warp_n = wid >> 2;
    const int blockRow = blockIdx.x * 128;

    float acc[2][NF][4];
#pragma unroll
    for (int i = 0; i < 2; i++)
#pragma unroll
        for (int j = 0; j < NF; j++)
#pragma unroll
            for (int q = 0; q < 4; q++) acc[i][j][q] = 0.f;

    auto A_hi = [&](int b) { return sm + b * BUF_EL; };
    auto A_lo = [&](int b) { return sm + b * BUF_EL + A_EL; };
    auto B_hi = [&](int b) { return sm + b * BUF_EL + 2 * A_EL; };
    auto B_lo = [&](int b) { return sm + b * BUF_EL + 2 * A_EL + B_EL; };

    float4 areg[4];
    auto loadA = [&](int k0) {
#pragma unroll
        for (int p = 0; p < 4; p++) {
            int v = p * 256 + tid;
            int r = v >> 3, cq = (v & 7) * 4;
            int grow = blockRow + r;
            areg[p] = (grow < M)
                ? *(const float4*)(A + (size_t)grow * K + k0 + cq)
                : make_float4(0.f, 0.f, 0.f, 0.f);
        }
    };
    auto storeA = [&](int b) {
        __nv_bfloat16* ah = A_hi(b);
        __nv_bfloat16* al = A_lo(b);
#pragma unroll
        for (int p = 0; p < 4; p++) {
            int v = p * 256 + tid;
            int r = v >> 3, cq = (v & 7) * 4;
            float4 x = areg[p];
            __nv_bfloat16 h0 = __float2bfloat16_rn(x.x);
            __nv_bfloat16 h1 = __float2bfloat16_rn(x.y);
            __nv_bfloat16 h2 = __float2bfloat16_rn(x.z);
            __nv_bfloat16 h3 = __float2bfloat16_rn(x.w);
            __nv_bfloat16 l0 = __float2bfloat16_rn(x.x - __bfloat162float(h0));
            __nv_bfloat16 l1 = __float2bfloat16_rn(x.y - __bfloat162float(h1));
            __nv_bfloat16 l2 = __float2bfloat16_rn(x.z - __bfloat162float(h2));
            __nv_bfloat16 l3 = __float2bfloat16_rn(x.w - __bfloat162float(h3));
            *(__nv_bfloat162*)(ah + r * APITCH + cq)     = __halves2bfloat162(h0, h1);
            *(__nv_bfloat162*)(ah + r * APITCH + cq + 2) = __halves2bfloat162(h2, h3);
            *(__nv_bfloat162*)(al + r * APITCH + cq)     = __halves2bfloat162(l0, l1);
            *(__nv_bfloat162*)(al + r * APITCH + cq + 2) = __halves2bfloat162(l2, l3);
        }
    };
    // 2 threads per row; each thread copies 16 halves (2 x 16B) per buffer.
    auto loadB = [&](int k0, int b) {
        int c = tid;
        if (BN_ == 64 && c >= 128) return;
        int n = c >> 1, kc = (c & 1) * 16;
        const __nv_bfloat16* gh = Bt_hi + (size_t)n * K + k0 + kc;
        const __nv_bfloat16* gl = Bt_lo + (size_t)n * K + k0 + kc;
        uint32_t sh = sptr(B_hi(b) + n * APITCH + kc);
        uint32_t sl = sptr(B_lo(b) + n * APITCH + kc);
        cp16(sh,      gh);
        cp16(sh + 16, gh + 8);
        cp16(sl,      gl);
        cp16(sl + 16, gl + 8);
    };
    auto compute = [&](int b) {
#pragma unroll
        for (int kk = 0; kk < 32; kk += 16) {
            uint32_t aH[2][4], aL[2][4];
            {
                int row = warp_m * 32 + (lane & 15);
                int col = kk + ((lane >> 4) << 3);
#pragma unroll
                for (int fm = 0; fm < 2; fm++) {
                    ldm4(aH[fm], sptr(A_hi(b) + (row + fm * 16) * APITCH + col));
                    ldm4(aL[fm], sptr(A_lo(b) + (row + fm * 16) * APITCH + col));
                }
            }
            uint32_t bH[NF][2], bL[NF][2];
            {
                int rbase = warp_n * (NF * 8) + (lane & 7) + ((lane >> 4) << 3);
                int col = kk + ((lane >> 3) & 1) * 8;
#pragma unroll
                for (int fp = 0; fp < NF / 2; fp++) {
                    uint32_t t[4];
                    ldm4(t, sptr(B_hi(b) + (rbase + fp * 16) * APITCH + col));
                    bH[fp * 2][0] = t[0]; bH[fp * 2][1] = t[1];
                    bH[fp * 2 + 1][0] = t[2]; bH[fp * 2 + 1][1] = t[3];
                    ldm4(t, sptr(B_lo(b) + (rbase + fp * 16) * APITCH + col));
                    bL[fp * 2][0] = t[0]; bL[fp * 2][1] = t[1];
                    bL[fp * 2 + 1][0] = t[2]; bL[fp * 2 + 1][1] = t[3];
                }
            }
#pragma unroll
            for (int fm = 0; fm < 2; fm++)
#pragma unroll
                for (int fn = 0; fn < NF; fn++) {
                    mma16816(acc[fm][fn], aH[fm], bH[fn]);
                    mma16816(acc[fm][fn], aH[fm], bL[fn]);
                    mma16816(acc[fm][fn], aL[fm], bH[fn]);
                }
        }
    };

    // ---- pipelined mainloop ----
    const int KB = K >> 5;
    loadA(0);
    loadB(0, 0);
    cp_commit();
    storeA(0);
    cp_wait0();
    __syncthreads();

    int buf = 0;
    for (int kb = 0; kb < KB; kb++) {
        const bool has_next = (kb + 1 < KB);
        if (has_next) {
            loadA((kb + 1) * 32);
            loadB((kb + 1) * 32, buf ^ 1);
            cp_commit();
        }
        compute(buf);
        if (has_next) {
            storeA(buf ^ 1);
            cp_wait0();
            __syncthreads();
        }
        buf ^= 1;
    }

    // ---- epilogue: bias (+relu), float2 stores ----
#pragma unroll
    for (int fm = 0; fm < 2; fm++) {
#pragma unroll
        for (int fn = 0; fn < NF; fn++) {
            int gn = warp_n * (NF * 8) + fn * 8 + (lane & 3) * 2;
            float2 bv = *(const float2*)(bias + gn);
            int gm0 = blockRow + warp_m * 32 + fm * 16 + (lane >> 2);
            float2 v0, v1;
            v0.x = acc[fm][fn][0] + bv.x;
            v0.y = acc[fm][fn][1] + bv.y;
            v1.x = acc[fm][fn][2] + bv.x;
            v1.y = acc[fm][fn][3] + bv.y;
            if (relu) {
                v0.x = fmaxf(v0.x, 0.f); v0.y = fmaxf(v0.y, 0.f);
                v1.x = fmaxf(v1.x, 0.f); v1.y = fmaxf(v1.y, 0.f);
            }
            if (gm0 < M)     *(float2*)(C + (size_t)gm0 * BN_ + gn) = v0;
            if (gm0 + 8 < M) *(float2*)(C + (size_t)(gm0 + 8) * BN_ + gn) = v1;
        }
    }
}

// ---------------------------------------------------------------------------
// All-weights transpose + bf16 hi/lo split into packed buffer.
// ---------------------------------------------------------------------------
__global__ void wsplit_all(const float* __restrict__ W0, const float* __restrict__ W1,
                           const float* __restrict__ W2, const float* __restrict__ f1,
                           const float* __restrict__ f2, const float* __restrict__ f3,
                           __nv_bfloat16* __restrict__ hi, __nv_bfloat16* __restrict__ lo)
{
    int i = blockIdx.x * blockDim.x + threadIdx.x;
    if (i >= WTOT) return;
    const float* w; int K, Nn, base;
    if      (i < WOFF_W1)  { w = W0; K = FIN; Nn = HH; base = WOFF_W0;  }
    else if (i < WOFF_W2)  { w = W1; K = HH;  Nn = HH; base = WOFF_W1;  }
    else if (i < WOFF_FC1) { w = W2; K = HH;  Nn = HH; base = WOFF_W2;  }
    else if (i < WOFF_FC2) { w = f1; K = HH;  Nn = HH; base = WOFF_FC1; }
    else if (i < WOFF_FC3) { w = f2; K = HH;  Nn = HH; base = WOFF_FC2; }
    else                   { w = f3; K = HH;  Nn = CC; base = WOFF_FC3; }
    int j = i - base;
    int k = j / Nn, n = j % Nn;
    float v = w[j];
    __nv_bfloat16 h = __float2bfloat16_rn(v);
    hi[base + (size_t)n * K + k] = h;
    lo[base + (size_t)n * K + k] = __float2bfloat16_rn(v - __bfloat162float(h));
}

// ---------------------------------------------------------------------------
// CSR build: histogram -> scan -> fill (edges sorted by dst)
// ---------------------------------------------------------------------------
__global__ void deg_count(const int* __restrict__ dst, int* __restrict__ rowptr, int E)
{
    int e = blockIdx.x * blockDim.x + threadIdx.x;
    if (e < E) atomicAdd(&rowptr[dst[e] + 1], 1);
}

__global__ __launch_bounds__(1024) void scan1(int* __restrict__ arr,
                                              int* __restrict__ bsum, int n)
{
    __shared__ int s[1024];
    int tid = threadIdx.x;
    int i = blockIdx.x * 1024 + tid;
    int v = (i < n) ? arr[i] : 0;
    s[tid] = v;
    __syncthreads();
#pragma unroll
    for (int off = 1; off < 1024; off <<= 1) {
        int t = (tid >= off) ? s[tid - off] : 0;
        __syncthreads();
        s[tid] += t;
        __syncthreads();
    }
    if (i < n) arr[i] = s[tid];
    if (tid == 1023) bsum[blockIdx.x] = s[1023];
}

__global__ void scan2(int* __restrict__ bsum, int nb)
{
    if (threadIdx.x == 0 && blockIdx.x == 0) {
        int run = 0;
        for (int i = 0; i < nb; i++) { int v = bsum[i]; bsum[i] = run; run += v; }
    }
}

__global__ __launch_bounds__(1024) void scan3(int* __restrict__ arr,
                                              const int* __restrict__ bsum, int n)
{
    int i = blockIdx.x * 1024 + threadIdx.x;
    if (i < n) arr[i] += bsum[blockIdx.x];
}

__global__ void fin_deg(const int* __restrict__ rowptr, float* __restrict__ dinv,
                        int* __restrict__ cursor, int n)
{
    int i = blockIdx.x * blockDim.x + threadIdx.x;
    if (i < n) {
        int beg = rowptr[i];
        int deg = rowptr[i + 1] - beg;
        dinv[i] = rsqrtf((float)deg + 1.0f);
        cursor[i] = beg;
    }
}

__global__ void fill_csr(const int* __restrict__ src, const int* __restrict__ dst,
                         const float* __restrict__ dinv, int* __restrict__ cursor,
                         int* __restrict__ csr_src, float* __restrict__ csr_norm, int E)
{
    int e = blockIdx.x * blockDim.x + threadIdx.x;
    if (e >= E) return;
    int s = src[e];
    int d = dst[e];
    int pos = atomicAdd(&cursor[d], 1);
    csr_src[pos] = s;
    csr_norm[pos] = dinv[s] * dinv[d];
}

// ---------------------------------------------------------------------------
// Gather aggregation: y[node] = relu(sum_e h[src_e]*norm_e + h[node]*dinv^2)
// ---------------------------------------------------------------------------
__global__ __launch_bounds__(256) void gather_conv(
    const float* __restrict__ h, const int* __restrict__ csr_src,
    const float* __restrict__ csr_norm, const int* __restrict__ rowptr,
    const float* __restrict__ dinv, float* __restrict__ y, int N)
{
    int node = blockIdx.x * 8 + (threadIdx.x >> 5);
    if (node >= N) return;
    int lane = threadIdx.x & 31;

    int beg = rowptr[node];
    int end = rowptr[node + 1];
    float di = dinv[node];
    float w = di * di;

    float4 self = *(const float4*)(h + (size_t)node * HH + lane * 4);
    float4 acc;
    acc.x = self.x * w; acc.y = self.y * w;
    acc.z = self.z * w; acc.w = self.w * w;

    for (int e = beg; e < end; e++) {
        int s = __ldg(csr_src + e);
        float nm = __ldg(csr_norm + e);
        float4 v = *(const float4*)(h + (size_t)s * HH + lane * 4);
        acc.x = fmaf(v.x, nm, acc.x);
        acc.y = fmaf(v.y, nm, acc.y);
        acc.z = fmaf(v.z, nm, acc.z);
        acc.w = fmaf(v.w, nm, acc.w);
    }
    acc.x = fmaxf(acc.x, 0.f);
    acc.y = fmaxf(acc.y, 0.f);
    acc.z = fmaxf(acc.z, 0.f);
    acc.w = fmaxf(acc.w, 0.f);
    *(float4*)(y + (size_t)node * HH + lane * 4) = acc;
}

// ---------------------------------------------------------------------------
// log_softmax over C=64 classes; 1 warp per row, 2 classes per lane.
// ---------------------------------------------------------------------------
__global__ void log_softmax_k(const float* __restrict__ logits, float* __restrict__ out, int N)
{
    int row = blockIdx.x * blockDim.y + threadIdx.y;
    if (row >= N) return;
    int lane = threadIdx.x;
    const float* lr = logits + (size_t)row * CC;
    float v0 = lr[lane], v1 = lr[lane + 32];
    float m = fmaxf(v0, v1);
#pragma unroll
    for (int o = 16; o; o >>= 1) m = fmaxf(m, __shfl_xor_sync(0xffffffffu, m, o));
    float s = expf(v0 - m) + expf(v1 - m);
#pragma unroll
    for (int o = 16; o; o >>= 1) s += __shfl_xor_sync(0xffffffffu, s, o);
    float ls = m + logf(s);
    float* orow = out + (size_t)row * CC;
    orow[lane] = v0 - ls;
    orow[lane + 32] = v1 - ls;
}

// ---------------------------------------------------------------------------
// Launch
// ---------------------------------------------------------------------------
extern "C" void kernel_launch(void* const* d_in, const int* in_sizes, int n_in,
                              void* d_out, int out_size)
{
    const float* x     = (const float*)d_in[0];
    const int*   ei    = (const int*)d_in[1];
    const float* W0    = (const float*)d_in[2];
    const float* b0    = (const float*)d_in[3];
    const float* W1    = (const float*)d_in[4];
    const float* b1    = (const float*)d_in[5];
    const float* W2    = (const float*)d_in[6];
    const float* b2    = (const float*)d_in[7];
    const float* fc1_w = (const float*)d_in[8];
    const float* fc1_b = (const float*)d_in[9];
    const float* fc2_w = (const float*)d_in[10];
    const float* fc2_b = (const float*)d_in[11];
    const float* fc3_w = (const float*)d_in[12];
    const float* fc3_b = (const float*)d_in[13];

    const int N = in_sizes[0] / FIN;   // 100000
    const int E = in_sizes[1] / 2;     // 1600000
    const int* src = ei;
    const int* dst = ei + E;

    float *h_, *y_, *dinv_, *csr_norm_;
    int *rowptr_, *cursor_, *csr_src_, *bsum_;
    __nv_bfloat16 *wthi_, *wtlo_;
    cudaGetSymbolAddress((void**)&h_,        g_h);
    cudaGetSymbolAddress((void**)&y_,        g_y);
    cudaGetSymbolAddress((void**)&dinv_,     g_dinv);
    cudaGetSymbolAddress((void**)&rowptr_,   g_rowptr);
    cudaGetSymbolAddress((void**)&cursor_,   g_cursor);
    cudaGetSymbolAddress((void**)&csr_src_,  g_csr_src);
    cudaGetSymbolAddress((void**)&csr_norm_, g_csr_norm);
    cudaGetSymbolAddress((void**)&bsum_,     g_bsum);
    cudaGetSymbolAddress((void**)&wthi_,     g_wthi);
    cudaGetSymbolAddress((void**)&wtlo_,     g_wtlo);

    constexpr int SMEM128 = (2 * (2 * 128 * APITCH + 2 * 128 * APITCH)) * 2; // 81920
    constexpr int SMEM64  = (2 * (2 * 128 * APITCH + 2 * 64  * APITCH)) * 2; // 61440
    cudaFuncSetAttribute(bf16_gemm<128>, cudaFuncAttributeMaxDynamicSharedMemorySize, SMEM128);
    cudaFuncSetAttribute(bf16_gemm<64>,  cudaFuncAttributeMaxDynamicSharedMemorySize, SMEM64);

    const int T = 256;
    const int gemm_blocks = (N + 127) / 128;   // 782

    // ---- weight prep (one kernel) ----
    wsplit_all<<<(WTOT + T - 1) / T, T>>>(W0, W1, W2, fc1_w, fc2_w, fc3_w, wthi_, wtlo_);

    // ---- CSR build + normalization ----
    const int np1 = N + 1;
    const int nb = (np1 + 1023) / 1024;
    cudaMemsetAsync(rowptr_, 0, (size_t)np1 * sizeof(int));
    deg_count<<<(E + T - 1) / T, T>>>(dst, rowptr_, E);
    scan1<<<nb, 1024>>>(rowptr_, bsum_, np1);
    scan2<<<1, 32>>>(bsum_, nb);
    scan3<<<nb, 1024>>>(rowptr_, bsum_, np1);
    fin_deg<<<(N + T - 1) / T, T>>>(rowptr_, dinv_, cursor_, N);
    fill_csr<<<(E + T - 1) / T, T>>>(src, dst, dinv_, cursor_, csr_src_, csr_norm_, E);

    const int gather_blocks = (N + 7) / 8;

    // ---- conv0 ----
    bf16_gemm<128><<<gemm_blocks, T, SMEM128>>>(x, wthi_ + WOFF_W0, wtlo_ + WOFF_W0, b0, h_, N, FIN, 0);
    gather_conv<<<gather_blocks, T>>>(h_, csr_src_, csr_norm_, rowptr_, dinv_, y_, N);

    // ---- conv1 ----
    bf16_gemm<128><<<gemm_blocks, T, SMEM128>>>(y_, wthi_ + WOFF_W1, wtlo_ + WOFF_W1, b1, h_, N, HH, 0);
    gather_conv<<<gather_blocks, T>>>(h_, csr_src_, csr_norm_, rowptr_, dinv_, y_, N);

    // ---- conv2 ----
    bf16_gemm<128><<<gemm_blocks, T, SMEM128>>>(y_, wthi_ + WOFF_W2, wtlo_ + WOFF_W2, b2, h_, N, HH, 0);
    gather_conv<<<gather_blocks, T>>>(h_, csr_src_, csr_norm_, rowptr_, dinv_, y_, N);

    // ---- MLP ----
    bf16_gemm<128><<<gemm_blocks, T, SMEM128>>>(y_, wthi_ + WOFF_FC1, wtlo_ + WOFF_FC1, fc1_b, h_, N, HH, 1);
    bf16_gemm<128><<<gemm_blocks, T, SMEM128>>>(h_, wthi_ + WOFF_FC2, wtlo_ + WOFF_FC2, fc2_b, y_, N, HH, 1);
    bf16_gemm<64><<<gemm_blocks, T, SMEM64>>>(y_, wthi_ + WOFF_FC3, wtlo_ + WOFF_FC3, fc3_b, h_, N, HH, 0);

    // ---- log_softmax ----
    dim3 ls_block(32, 8);
    log_softmax_k<<<(N + 7) / 8, ls_block>>>(h_, (float*)d_out, N);
}

// round 13
// speedup vs baseline: 2.8464x; 1.0761x over previous
#include <cuda_runtime.h>
#include <cuda_bf16.h>
#include <math.h>
#include <stdint.h>

// Problem constants (fixed by reference)
constexpr int NN  = 100000;
constexpr int EE  = 1600000;
constexpr int FIN = 512;
constexpr int HH  = 128;
constexpr int CC  = 64;

// Packed transposed/split weight buffer segment bases (elements)
constexpr int WOFF_W0  = 0;         // 512x128
constexpr int WOFF_W1  = 65536;     // 128x128
constexpr int WOFF_W2  = 81920;
constexpr int WOFF_FC1 = 98304;
constexpr int WOFF_FC2 = 114688;
constexpr int WOFF_FC3 = 131072;    // 128x64
constexpr int WTOT     = 139264;

// Scratch (device globals: allocation-free rule)
__device__ float g_h[(size_t)NN * HH];
__device__ float g_y[(size_t)NN * HH];
__device__ float g_dinv[NN];
__device__ int   g_rowptr[NN + 1];
__device__ int   g_cursor[NN];
__device__ int   g_csr_src[EE];
__device__ float g_csr_norm[EE];
__device__ int   g_bsum[256];
__device__ __nv_bfloat16 g_wthi[WTOT];
__device__ __nv_bfloat16 g_wtlo[WTOT];

// ---------------------------------------------------------------------------
// PTX helpers (baseline ISA; compiles for compute_103)
// ---------------------------------------------------------------------------
__device__ __forceinline__ uint32_t sptr(const void* p) {
    return (uint32_t)__cvta_generic_to_shared(p);
}
__device__ __forceinline__ void ldm4(uint32_t* r, uint32_t addr) {
    asm volatile("ldmatrix.sync.aligned.m8n8.x4.shared.b16 {%0,%1,%2,%3}, [%4];"
                 : "=r"(r[0]), "=r"(r[1]), "=r"(r[2]), "=r"(r[3]) : "r"(addr));
}
__device__ __forceinline__ void mma16816(float* c, const uint32_t* a, const uint32_t* b) {
    asm volatile(
        "mma.sync.aligned.m16n8k16.row.col.f32.bf16.bf16.f32 "
        "{%0,%1,%2,%3}, {%4,%5,%6,%7}, {%8,%9}, {%0,%1,%2,%3};"
        : "+f"(c[0]), "+f"(c[1]), "+f"(c[2]), "+f"(c[3])
        : "r"(a[0]), "r"(a[1]), "r"(a[2]), "r"(a[3]), "r"(b[0]), "r"(b[1]));
}
__device__ __forceinline__ void cp16(uint32_t saddr, const void* gaddr) {
    asm volatile("cp.async.ca.shared.global [%0], [%1], 16;"
                 :: "r"(saddr), "l"(gaddr) : "memory");
}
__device__ __forceinline__ void cp_commit() {
    asm volatile("cp.async.commit_group;" ::: "memory");
}
__device__ __forceinline__ void cp_wait0() {
    asm volatile("cp.async.wait_group 0;" ::: "memory");
}

// ---------------------------------------------------------------------------
// bf16 3-term split GEMM, software-pipelined (proven R11 version).
// ---------------------------------------------------------------------------
#define APITCH 40   // smem pitch in halves (80B; breaks ldmatrix bank conflicts)

template <int BN_>
__global__ __launch_bounds__(256, 2) void bf16_gemm(
    const float* __restrict__ A,
    const __nv_bfloat16* __restrict__ Bt_hi,
    const __nv_bfloat16* __restrict__ Bt_lo,
    const float* __restrict__ bias, float* __restrict__ C,
    int M, int K, int relu)
{
    constexpr int NF = BN_ / 16;
    constexpr int A_EL  = 128 * APITCH;
    constexpr int B_EL  = BN_ * APITCH;
    constexpr int BUF_EL = 2 * A_EL + 2 * B_EL;
    extern __shared__ __align__(16) __nv_bfloat16 sm[];

    const int tid  = threadIdx.x;
    const int wid  = tid >> 5;
    const int lane = tid & 31;
    const int warp_m = wid & 3;
    const int warp_n = wid >> 2;
    const int blockRow = blockIdx.x * 128;

    float acc[2][NF][4];
#pragma unroll
    for (int i = 0; i < 2; i++)
#pragma unroll
        for (int j = 0; j < NF; j++)
#pragma unroll
            for (int q = 0; q < 4; q++) acc[i][j][q] = 0.f;

    auto A_hi = [&](int b) { return sm + b * BUF_EL; };
    auto A_lo = [&](int b) { return sm + b * BUF_EL + A_EL; };
    auto B_hi = [&](int b) { return sm + b * BUF_EL + 2 * A_EL; };
    auto B_lo = [&](int b) { return sm + b * BUF_EL + 2 * A_EL + B_EL; };

    float4 areg[4];
    auto loadA = [&](int k0) {
#pragma unroll
        for (int p = 0; p < 4; p++) {
            int v = p * 256 + tid;
            int r = v >> 3, cq = (v & 7) * 4;
            int grow = blockRow + r;
            areg[p] = (grow < M)
                ? *(const float4*)(A + (size_t)grow * K + k0 + cq)
                : make_float4(0.f, 0.f, 0.f, 0.f);
        }
    };
    auto storeA = [&](int b) {
        __nv_bfloat16* ah = A_hi(b);
        __nv_bfloat16* al = A_lo(b);
#pragma unroll
        for (int p = 0; p < 4; p++) {
            int v = p * 256 + tid;
            int r = v >> 3, cq = (v & 7) * 4;
            float4 x = areg[p];
            __nv_bfloat16 h0 = __float2bfloat16_rn(x.x);
            __nv_bfloat16 h1 = __float2bfloat16_rn(x.y);
            __nv_bfloat16 h2 = __float2bfloat16_rn(x.z);
            __nv_bfloat16 h3 = __float2bfloat16_rn(x.w);
            __nv_bfloat16 l0 = __float2bfloat16_rn(x.x - __bfloat162float(h0));
            __nv_bfloat16 l1 = __float2bfloat16_rn(x.y - __bfloat162float(h1));
            __nv_bfloat16 l2 = __float2bfloat16_rn(x.z - __bfloat162float(h2));
            __nv_bfloat16 l3 = __float2bfloat16_rn(x.w - __bfloat162float(h3));
            *(__nv_bfloat162*)(ah + r * APITCH + cq)     = __halves2bfloat162(h0, h1);
            *(__nv_bfloat162*)(ah + r * APITCH + cq + 2) = __halves2bfloat162(h2, h3);
            *(__nv_bfloat162*)(al + r * APITCH + cq)     = __halves2bfloat162(l0, l1);
            *(__nv_bfloat162*)(al + r * APITCH + cq + 2) = __halves2bfloat162(l2, l3);
        }
    };
    auto loadB = [&](int k0, int b) {
        int c = tid;
        if (BN_ == 64 && c >= 128) return;
        int n = c >> 1, kc = (c & 1) * 16;
        const __nv_bfloat16* gh = Bt_hi + (size_t)n * K + k0 + kc;
        const __nv_bfloat16* gl = Bt_lo + (size_t)n * K + k0 + kc;
        uint32_t sh = sptr(B_hi(b) + n * APITCH + kc);
        uint32_t sl = sptr(B_lo(b) + n * APITCH + kc);
        cp16(sh,      gh);
        cp16(sh + 16, gh + 8);
        cp16(sl,      gl);
        cp16(sl + 16, gl + 8);
    };
    auto compute = [&](int b) {
#pragma unroll
        for (int kk = 0; kk < 32; kk += 16) {
            uint32_t aH[2][4], aL[2][4];
            {
                int row = warp_m * 32 + (lane & 15);
                int col = kk + ((lane >> 4) << 3);
#pragma unroll
                for (int fm = 0; fm < 2; fm++) {
                    ldm4(aH[fm], sptr(A_hi(b) + (row + fm * 16) * APITCH + col));
                    ldm4(aL[fm], sptr(A_lo(b) + (row + fm * 16) * APITCH + col));
                }
            }
            uint32_t bH[NF][2], bL[NF][2];
            {
                int rbase = warp_n * (NF * 8) + (lane & 7) + ((lane >> 4) << 3);
                int col = kk + ((lane >> 3) & 1) * 8;
#pragma unroll
                for (int fp = 0; fp < NF / 2; fp++) {
                    uint32_t t[4];
                    ldm4(t, sptr(B_hi(b) + (rbase + fp * 16) * APITCH + col));
                    bH[fp * 2][0] = t[0]; bH[fp * 2][1] = t[1];
                    bH[fp * 2 + 1][0] = t[2]; bH[fp * 2 + 1][1] = t[3];
                    ldm4(t, sptr(B_lo(b) + (rbase + fp * 16) * APITCH + col));
                    bL[fp * 2][0] = t[0]; bL[fp * 2][1] = t[1];
                    bL[fp * 2 + 1][0] = t[2]; bL[fp * 2 + 1][1] = t[3];
                }
            }
#pragma unroll
            for (int fm = 0; fm < 2; fm++)
#pragma unroll
                for (int fn = 0; fn < NF; fn++) {
                    mma16816(acc[fm][fn], aH[fm], bH[fn]);
                    mma16816(acc[fm][fn], aH[fm], bL[fn]);
                    mma16816(acc[fm][fn], aL[fm], bH[fn]);
                }
        }
    };

    const int KB = K >> 5;
    loadA(0);
    loadB(0, 0);
    cp_commit();
    storeA(0);
    cp_wait0();
    __syncthreads();

    int buf = 0;
    for (int kb = 0; kb < KB; kb++) {
        const bool has_next = (kb + 1 < KB);
        if (has_next) {
            loadA((kb + 1) * 32);
            loadB((kb + 1) * 32, buf ^ 1);
            cp_commit();
        }
        compute(buf);
        if (has_next) {
            storeA(buf ^ 1);
            cp_wait0();
            __syncthreads();
        }
        buf ^= 1;
    }

#pragma unroll
    for (int fm = 0; fm < 2; fm++) {
#pragma unroll
        for (int fn = 0; fn < NF; fn++) {
            int gn = warp_n * (NF * 8) + fn * 8 + (lane & 3) * 2;
            float2 bv = *(const float2*)(bias + gn);
            int gm0 = blockRow + warp_m * 32 + fm * 16 + (lane >> 2);
            float2 v0, v1;
            v0.x = acc[fm][fn][0] + bv.x;
            v0.y = acc[fm][fn][1] + bv.y;
            v1.x = acc[fm][fn][2] + bv.x;
            v1.y = acc[fm][fn][3] + bv.y;
            if (relu) {
                v0.x = fmaxf(v0.x, 0.f); v0.y = fmaxf(v0.y, 0.f);
                v1.x = fmaxf(v1.x, 0.f); v1.y = fmaxf(v1.y, 0.f);
            }
            if (gm0 < M)     *(float2*)(C + (size_t)gm0 * BN_ + gn) = v0;
            if (gm0 + 8 < M) *(float2*)(C + (size_t)(gm0 + 8) * BN_ + gn) = v1;
        }
    }
}

// ---------------------------------------------------------------------------
// All-weights transpose + bf16 hi/lo split into packed buffer.
// ---------------------------------------------------------------------------
__global__ void wsplit_all(const float* __restrict__ W0, const float* __restrict__ W1,
                           const float* __restrict__ W2, const float* __restrict__ f1,
                           const float* __restrict__ f2, const float* __restrict__ f3,
                           __nv_bfloat16* __restrict__ hi, __nv_bfloat16* __restrict__ lo)
{
    int i = blockIdx.x * blockDim.x + threadIdx.x;
    if (i >= WTOT) return;
    const float* w; int K, Nn, base;
    if      (i < WOFF_W1)  { w = W0; K = FIN; Nn = HH; base = WOFF_W0;  }
    else if (i < WOFF_W2)  { w = W1; K = HH;  Nn = HH; base = WOFF_W1;  }
    else if (i < WOFF_FC1) { w = W2; K = HH;  Nn = HH; base = WOFF_W2;  }
    else if (i < WOFF_FC2) { w = f1; K = HH;  Nn = HH; base = WOFF_FC1; }
    else if (i < WOFF_FC3) { w = f2; K = HH;  Nn = HH; base = WOFF_FC2; }
    else                   { w = f3; K = HH;  Nn = CC; base = WOFF_FC3; }
    int j = i - base;
    int k = j / Nn, n = j % Nn;
    float v = w[j];
    __nv_bfloat16 h = __float2bfloat16_rn(v);
    hi[base + (size_t)n * K + k] = h;
    lo[base + (size_t)n * K + k] = __float2bfloat16_rn(v - __bfloat162float(h));
}

// ---------------------------------------------------------------------------
// CSR build: histogram -> scan -> fill (edges sorted by dst)
// ---------------------------------------------------------------------------
__global__ void deg_count(const int* __restrict__ dst, int* __restrict__ rowptr, int E)
{
    int e = blockIdx.x * blockDim.x + threadIdx.x;
    if (e < E) atomicAdd(&rowptr[dst[e] + 1], 1);
}

__global__ __launch_bounds__(1024) void scan1(int* __restrict__ arr,
                                              int* __restrict__ bsum, int n)
{
    __shared__ int s[1024];
    int tid = threadIdx.x;
    int i = blockIdx.x * 1024 + tid;
    int v = (i < n) ? arr[i] : 0;
    s[tid] = v;
    __syncthreads();
#pragma unroll
    for (int off = 1; off < 1024; off <<= 1) {
        int t = (tid >= off) ? s[tid - off] : 0;
        __syncthreads();
        s[tid] += t;
        __syncthreads();
    }
    if (i < n) arr[i] = s[tid];
    if (tid == 1023) bsum[blockIdx.x] = s[1023];
}

__global__ void scan2(int* __restrict__ bsum, int nb)
{
    if (threadIdx.x == 0 && blockIdx.x == 0) {
        int run = 0;
        for (int i = 0; i < nb; i++) { int v = bsum[i]; bsum[i] = run; run += v; }
    }
}

__global__ __launch_bounds__(1024) void scan3(int* __restrict__ arr,
                                              const int* __restrict__ bsum, int n)
{
    int i = blockIdx.x * 1024 + threadIdx.x;
    if (i < n) arr[i] += bsum[blockIdx.x];
}

__global__ void fin_deg(const int* __restrict__ rowptr, float* __restrict__ dinv,
                        int* __restrict__ cursor, int n)
{
    int i = blockIdx.x * blockDim.x + threadIdx.x;
    if (i < n) {
        int beg = rowptr[i];
        int deg = rowptr[i + 1] - beg;
        dinv[i] = rsqrtf((float)deg + 1.0f);
        cursor[i] = beg;
    }
}

__global__ void fill_csr(const int* __restrict__ src, const int* __restrict__ dst,
                         const float* __restrict__ dinv, int* __restrict__ cursor,
                         int* __restrict__ csr_src, float* __restrict__ csr_norm, int E)
{
    int e = blockIdx.x * blockDim.x + threadIdx.x;
    if (e >= E) return;
    int s = src[e];
    int d = dst[e];
    int pos = atomicAdd(&cursor[d], 1);
    csr_src[pos] = s;
    csr_norm[pos] = dinv[s] * dinv[d];
}

// ---------------------------------------------------------------------------
// Gather aggregation, edge-loop unrolled x4 for MLP:
//   y[node] = relu(sum_e h[src_e]*norm_e + h[node]*dinv^2)
// ---------------------------------------------------------------------------
__global__ __launch_bounds__(256) void gather_conv(
    const float* __restrict__ h, const int* __restrict__ csr_src,
    const float* __restrict__ csr_norm, const int* __restrict__ rowptr,
    const float* __restrict__ dinv, float* __restrict__ y, int N)
{
    int node = blockIdx.x * 8 + (threadIdx.x >> 5);
    if (node >= N) return;
    int lane = threadIdx.x & 31;

    int beg = rowptr[node];
    int end = rowptr[node + 1];
    float di = dinv[node];
    float w = di * di;

    const float* hl = h + lane * 4;
    float4 self = *(const float4*)(hl + (size_t)node * HH);
    float4 acc;
    acc.x = self.x * w; acc.y = self.y * w;
    acc.z = self.z * w; acc.w = self.w * w;

    int e = beg;
    for (; e + 3 < end; e += 4) {
        int s0 = __ldg(csr_src + e);
        int s1 = __ldg(csr_src + e + 1);
        int s2 = __ldg(csr_src + e + 2);
        int s3 = __ldg(csr_src + e + 3);
        float n0 = __ldg(csr_norm + e);
        float n1 = __ldg(csr_norm + e + 1);
        float n2 = __ldg(csr_norm + e + 2);
        float n3 = __ldg(csr_norm + e + 3);
        float4 v0 = *(const float4*)(hl + (size_t)s0 * HH);
        float4 v1 = *(const float4*)(hl + (size_t)s1 * HH);
        float4 v2 = *(const float4*)(hl + (size_t)s2 * HH);
        float4 v3 = *(const float4*)(hl + (size_t)s3 * HH);
        acc.x = fmaf(v0.x, n0, acc.x); acc.y = fmaf(v0.y, n0, acc.y);
        acc.z = fmaf(v0.z, n0, acc.z); acc.w = fmaf(v0.w, n0, acc.w);
        acc.x = fmaf(v1.x, n1, acc.x); acc.y = fmaf(v1.y, n1, acc.y);
        acc.z = fmaf(v1.z, n1, acc.z); acc.w = fmaf(v1.w, n1, acc.w);
        acc.x = fmaf(v2.x, n2, acc.x); acc.y = fmaf(v2.y, n2, acc.y);
        acc.z = fmaf(v2.z, n2, acc.z); acc.w = fmaf(v2.w, n2, acc.w);
        acc.x = fmaf(v3.x, n3, acc.x); acc.y = fmaf(v3.y, n3, acc.y);
        acc.z = fmaf(v3.z, n3, acc.z); acc.w = fmaf(v3.w, n3, acc.w);
    }
    for (; e < end; e++) {
        int s = __ldg(csr_src + e);
        float nm = __ldg(csr_norm + e);
        float4 v = *(const float4*)(hl + (size_t)s * HH);
        acc.x = fmaf(v.x, nm, acc.x);
        acc.y = fmaf(v.y, nm, acc.y);
        acc.z = fmaf(v.z, nm, acc.z);
        acc.w = fmaf(v.w, nm, acc.w);
    }
    acc.x = fmaxf(acc.x, 0.f);
    acc.y = fmaxf(acc.y, 0.f);
    acc.z = fmaxf(acc.z, 0.f);
    acc.w = fmaxf(acc.w, 0.f);
    *(float4*)(y + (size_t)node * HH + lane * 4) = acc;
}

// ---------------------------------------------------------------------------
// log_softmax over C=64 classes; 1 warp per row, 2 classes per lane.
// ---------------------------------------------------------------------------
__global__ void log_softmax_k(const float* __restrict__ logits, float* __restrict__ out, int N)
{
    int row = blockIdx.x * blockDim.y + threadIdx.y;
    if (row >= N) return;
    int lane = threadIdx.x;
    const float* lr = logits + (size_t)row * CC;
    float v0 = lr[lane], v1 = lr[lane + 32];
    float m = fmaxf(v0, v1);
#pragma unroll
    for (int o = 16; o; o >>= 1) m = fmaxf(m, __shfl_xor_sync(0xffffffffu, m, o));
    float s = expf(v0 - m) + expf(v1 - m);
#pragma unroll
    for (int o = 16; o; o >>= 1) s += __shfl_xor_sync(0xffffffffu, s, o);
    float ls = m + logf(s);
    float* orow = out + (size_t)row * CC;
    orow[lane] = v0 - ls;
    orow[lane + 32] = v1 - ls;
}

// ---------------------------------------------------------------------------
// Launch — CSR build overlapped with weight prep + conv0 GEMM on a 2nd stream.
// ---------------------------------------------------------------------------
extern "C" void kernel_launch(void* const* d_in, const int* in_sizes, int n_in,
                              void* d_out, int out_size)
{
    const float* x     = (const float*)d_in[0];
    const int*   ei    = (const int*)d_in[1];
    const float* W0    = (const float*)d_in[2];
    const float* b0    = (const float*)d_in[3];
    const float* W1    = (const float*)d_in[4];
    const float* b1    = (const float*)d_in[5];
    const float* W2    = (const float*)d_in[6];
    const float* b2    = (const float*)d_in[7];
    const float* fc1_w = (const float*)d_in[8];
    const float* fc1_b = (const float*)d_in[9];
    const float* fc2_w = (const float*)d_in[10];
    const float* fc2_b = (const float*)d_in[11];
    const float* fc3_w = (const float*)d_in[12];
    const float* fc3_b = (const float*)d_in[13];

    const int N = in_sizes[0] / FIN;   // 100000
    const int E = in_sizes[1] / 2;     // 1600000
    const int* src = ei;
    const int* dst = ei + E;

    float *h_, *y_, *dinv_, *csr_norm_;
    int *rowptr_, *cursor_, *csr_src_, *bsum_;
    __nv_bfloat16 *wthi_, *wtlo_;
    cudaGetSymbolAddress((void**)&h_,        g_h);
    cudaGetSymbolAddress((void**)&y_,        g_y);
    cudaGetSymbolAddress((void**)&dinv_,     g_dinv);
    cudaGetSymbolAddress((void**)&rowptr_,   g_rowptr);
    cudaGetSymbolAddress((void**)&cursor_,   g_cursor);
    cudaGetSymbolAddress((void**)&csr_src_,  g_csr_src);
    cudaGetSymbolAddress((void**)&csr_norm_, g_csr_norm);
    cudaGetSymbolAddress((void**)&bsum_,     g_bsum);
    cudaGetSymbolAddress((void**)&wthi_,     g_wthi);
    cudaGetSymbolAddress((void**)&wtlo_,     g_wtlo);

    constexpr int SMEM128 = (2 * (2 * 128 * APITCH + 2 * 128 * APITCH)) * 2; // 81920
    constexpr int SMEM64  = (2 * (2 * 128 * APITCH + 2 * 64  * APITCH)) * 2; // 61440
    cudaFuncSetAttribute(bf16_gemm<128>, cudaFuncAttributeMaxDynamicSharedMemorySize, SMEM128);
    cudaFuncSetAttribute(bf16_gemm<64>,  cudaFuncAttributeMaxDynamicSharedMemorySize, SMEM64);

    // One-time stream/event creation (host-side; no device memory involved)
    static cudaStream_t s_pre = nullptr;
    static cudaEvent_t ev_fork = nullptr, ev_join = nullptr;
    if (s_pre == nullptr) {
        cudaStreamCreateWithFlags(&s_pre, cudaStreamNonBlocking);
        cudaEventCreateWithFlags(&ev_fork, cudaEventDisableTiming);
        cudaEventCreateWithFlags(&ev_join, cudaEventDisableTiming);
    }

    const int T = 256;
    const int gemm_blocks = (N + 127) / 128;   // 782
    const int np1 = N + 1;
    const int nb = (np1 + 1023) / 1024;

    // ---- fork: CSR build on s_pre, weight prep + conv0 GEMM on main ----
    cudaEventRecord(ev_fork, 0);
    cudaStreamWaitEvent(s_pre, ev_fork, 0);

    cudaMemsetAsync(rowptr_, 0, (size_t)np1 * sizeof(int), s_pre);
    deg_count<<<(E + T - 1) / T, T, 0, s_pre>>>(dst, rowptr_, E);
    scan1<<<nb, 1024, 0, s_pre>>>(rowptr_, bsum_, np1);
    scan2<<<1, 32, 0, s_pre>>>(bsum_, nb);
    scan3<<<nb, 1024, 0, s_pre>>>(rowptr_, bsum_, np1);
    fin_deg<<<(N + T - 1) / T, T, 0, s_pre>>>(rowptr_, dinv_, cursor_, N);
    fill_csr<<<(E + T - 1) / T, T, 0, s_pre>>>(src, dst, dinv_, cursor_,
                                               csr_src_, csr_norm_, E);
    cudaEventRecord(ev_join, s_pre);

    wsplit_all<<<(WTOT + T - 1) / T, T>>>(W0, W1, W2, fc1_w, fc2_w, fc3_w, wthi_, wtlo_);
    bf16_gemm<128><<<gemm_blocks, T, SMEM128>>>(x, wthi_ + WOFF_W0, wtlo_ + WOFF_W0,
                                                b0, h_, N, FIN, 0);

    // ---- join: gathers need CSR ----
    cudaStreamWaitEvent(0, ev_join, 0);

    const int gather_blocks = (N + 7) / 8;

    gather_conv<<<gather_blocks, T>>>(h_, csr_src_, csr_norm_, rowptr_, dinv_, y_, N);

    bf16_gemm<128><<<gemm_blocks, T, SMEM128>>>(y_, wthi_ + WOFF_W1, wtlo_ + WOFF_W1, b1, h_, N, HH, 0);
    gather_conv<<<gather_blocks, T>>>(h_, csr_src_, csr_norm_, rowptr_, dinv_, y_, N);

    bf16_gemm<128><<<gemm_blocks, T, SMEM128>>>(y_, wthi_ + WOFF_W2, wtlo_ + WOFF_W2, b2, h_, N, HH, 0);
    gather_conv<<<gather_blocks, T>>>(h_, csr_src_, csr_norm_, rowptr_, dinv_, y_, N);

    bf16_gemm<128><<<gemm_blocks, T, SMEM128>>>(y_, wthi_ + WOFF_FC1, wtlo_ + WOFF_FC1, fc1_b, h_, N, HH, 1);
    bf16_gemm<128><<<gemm_blocks, T, SMEM128>>>(h_, wthi_ + WOFF_FC2, wtlo_ + WOFF_FC2, fc2_b, y_, N, HH, 1);
    bf16_gemm<64><<<gemm_blocks, T, SMEM64>>>(y_, wthi_ + WOFF_FC3, wtlo_ + WOFF_FC3, fc3_b, h_, N, HH, 0);

    // ---- log_softmax ----
    dim3 ls_block(32, 8);
    log_softmax_k<<<(N + 7) / 8, ls_block>>>(h_, (float*)d_out, N);
}